// round 12
// baseline (speedup 1.0000x reference)
#include <cuda_runtime.h>
#include <math.h>

#define Bsz 8
#define Nn  1024
#define Dd  256
#define Hh  512
#define Mm  256
#define Oo  256
#define MN  (Bsz*Nn)
#define LSTM_CTAS 64
#define LSTM_THREADS 512

#define FMA2(d,a,b,c) asm("fma.rn.f32x2 %0, %1, %2, %3;" \
    : "=l"(d) : "l"(a), "l"(b), "l"(c))

__device__ float g_xproj[(size_t)MN*4*Hh];
__device__ float g_h[(size_t)MN*Hh];
__device__ float g_scores[(size_t)Bsz*Nn*Nn];
__device__ float g_sagg[(size_t)MN*Hh];
__device__ float g_t1[(size_t)MN*Mm];
__device__ float g_t2[(size_t)MN*Mm];
__device__ float g_ax[(size_t)MN*Mm];
__device__ float g_av[(size_t)MN*Mm];
__device__ float g_agg[(size_t)MN*Oo];
__device__ float g_bsum[4*Hh];
__device__ float g_hbuf[2][Bsz*Hh];
__device__ int   g_hasnb[MN];
__device__ unsigned g_bar_in = 0;
__device__ unsigned g_bar_epoch = 0;

__global__ void bsum_kernel(const float* __restrict__ a, const float* __restrict__ b) {
    int i = blockIdx.x * 256 + threadIdx.x;
    if (i < 4*Hh) g_bsum[i] = a[i] + b[i];
}

__global__ void zeroagg_kernel() {
    int row = blockIdx.x;
    if (!g_hasnb[row]) g_agg[(size_t)row*Oo + threadIdx.x] = 0.f;
}

// C = A * op(B) (+bias)(ReLU)(+=C). 128x128 tile, K-tile 8, 256 thr, 8x8 micro.
// 2-stage double-buffered smem pipeline; packed f32x2 FMA.
template<int TRANSB, int RELU>
__global__ __launch_bounds__(256)
void sgemm(const float* __restrict__ A, const float* __restrict__ B,
           const float* __restrict__ bias, float* __restrict__ C,
           int K, int lda, int ldb, int ldc,
           long long sA, long long sB, long long sC, int beta)
{
    __shared__ float As[2][8][132];
    __shared__ float Bs[2][8][132];
    const int tid = threadIdx.x;
    const int m0 = blockIdx.y * 128, n0 = blockIdx.x * 128;
    A += (long long)blockIdx.z * sA;
    B += (long long)blockIdx.z * sB;
    C += (long long)blockIdx.z * sC;

    unsigned long long pacc[8][4];
#pragma unroll
    for (int i = 0; i < 8; i++)
#pragma unroll
        for (int j = 0; j < 4; j++) pacc[i][j] = 0ull;

    const int ty = tid >> 4, tx = tid & 15;
    const int am = tid >> 1, akq = (tid & 1) * 4;
    const int bk = tid >> 5, bnq = (tid & 31) * 4;

    // prefetch tile 0
    float4 pa = *(const float4*)&A[(size_t)(m0 + am) * lda + akq];
    float4 pb;
    if (TRANSB) pb = *(const float4*)&B[(size_t)(n0 + am) * ldb + akq];
    else        pb = *(const float4*)&B[(size_t)bk * ldb + n0 + bnq];

    int cur = 0;
    As[0][akq+0][am] = pa.x; As[0][akq+1][am] = pa.y;
    As[0][akq+2][am] = pa.z; As[0][akq+3][am] = pa.w;
    if (TRANSB) {
        Bs[0][akq+0][am] = pb.x; Bs[0][akq+1][am] = pb.y;
        Bs[0][akq+2][am] = pb.z; Bs[0][akq+3][am] = pb.w;
    } else {
        *(float4*)&Bs[0][bk][bnq] = pb;
    }
    __syncthreads();

    const int NT = K >> 3;
    for (int kt = 0; kt < NT; kt++) {
        if (kt + 1 < NT) {
            int k0 = (kt + 1) << 3;
            pa = *(const float4*)&A[(size_t)(m0 + am) * lda + k0 + akq];
            if (TRANSB) pb = *(const float4*)&B[(size_t)(n0 + am) * ldb + k0 + akq];
            else        pb = *(const float4*)&B[(size_t)(k0 + bk) * ldb + n0 + bnq];
        }
#pragma unroll
        for (int k = 0; k < 8; k++) {
            float a[8];
            *(float4*)&a[0] = *(const float4*)&As[cur][k][ty*8];
            *(float4*)&a[4] = *(const float4*)&As[cur][k][ty*8 + 4];
            ulonglong2 q0 = *(const ulonglong2*)&Bs[cur][k][tx*8];
            ulonglong2 q1 = *(const ulonglong2*)&Bs[cur][k][tx*8 + 4];
            unsigned long long bp0 = q0.x, bp1 = q0.y, bp2 = q1.x, bp3 = q1.y;
#pragma unroll
            for (int i = 0; i < 8; i++) {
                unsigned au = __float_as_uint(a[i]);
                unsigned long long ai;
                asm("mov.b64 %0, {%1, %1};" : "=l"(ai) : "r"(au));
                FMA2(pacc[i][0], ai, bp0, pacc[i][0]);
                FMA2(pacc[i][1], ai, bp1, pacc[i][1]);
                FMA2(pacc[i][2], ai, bp2, pacc[i][2]);
                FMA2(pacc[i][3], ai, bp3, pacc[i][3]);
            }
        }
        if (kt + 1 < NT) {
            int nxt = cur ^ 1;
            As[nxt][akq+0][am] = pa.x; As[nxt][akq+1][am] = pa.y;
            As[nxt][akq+2][am] = pa.z; As[nxt][akq+3][am] = pa.w;
            if (TRANSB) {
                Bs[nxt][akq+0][am] = pb.x; Bs[nxt][akq+1][am] = pb.y;
                Bs[nxt][akq+2][am] = pb.z; Bs[nxt][akq+3][am] = pb.w;
            } else {
                *(float4*)&Bs[nxt][bk][bnq] = pb;
            }
            __syncthreads();
            cur = nxt;
        }
    }

    float bv[8];
#pragma unroll
    for (int j = 0; j < 8; j++) bv[j] = bias ? bias[n0 + tx*8 + j] : 0.f;
#pragma unroll
    for (int i = 0; i < 8; i++) {
        float accf[8];
#pragma unroll
        for (int j4 = 0; j4 < 4; j4++) {
            float2 v = *(float2*)&pacc[i][j4];
            accf[2*j4]   = v.x;
            accf[2*j4+1] = v.y;
        }
        float* cp = C + (size_t)(m0 + ty*8 + i) * ldc + n0 + tx*8;
#pragma unroll
        for (int j = 0; j < 8; j += 4) {
            float4 r;
            r.x = accf[j+0] + bv[j+0]; r.y = accf[j+1] + bv[j+1];
            r.z = accf[j+2] + bv[j+2]; r.w = accf[j+3] + bv[j+3];
            if (RELU) {
                r.x = fmaxf(r.x, 0.f); r.y = fmaxf(r.y, 0.f);
                r.z = fmaxf(r.z, 0.f); r.w = fmaxf(r.w, 0.f);
            }
            if (beta) {
                float4 o = *(const float4*)(cp + j);
                r.x += o.x; r.y += o.y; r.z += o.z; r.w += o.w;
            }
            *(float4*)(cp + j) = r;
        }
    }
}

// Persistent LSTM: 64 CTAs x 512 threads. CTA c owns hidden units [8c,8c+8)
// -> 32 gate rows of W_hh in SMEM. R3-proven flat epoch barrier (count=64).
// Next-step xproj gate value prefetched into the barrier-spin window.
__global__ __launch_bounds__(LSTM_THREADS, 1)
void lstm_kernel(const float* __restrict__ W_hh)
{
    extern __shared__ float sh[];
    float* w_sm  = sh;                 // 32*516
    float* h_smb = w_sm + 32*516;      // 8*516
    float* red1  = h_smb + 8*516;      // 256
    float* gsm   = red1 + 256;         // 256
    float* c_sm  = gsm + 256;          // 64

    const int tid = threadIdx.x;
    const int cta = blockIdx.x;

    for (int i = tid; i < 32*512; i += LSTM_THREADS) {
        int r = i >> 9, k = i & 511;
        int grow = ((r & 3) << 9) + cta*8 + (r >> 2);   // gate*512 + unit
        w_sm[r*516 + k] = W_hh[(size_t)grow*Hh + k];
    }
    for (int i = tid; i < 8*516; i += LSTM_THREADS) h_smb[i] = 0.f;
    if (tid < 64) c_sm[tid] = 0.f;
    unsigned ep0 = atomicAdd(&g_bar_epoch, 0u);
    __syncthreads();

    const int khalf = tid >> 8;        // 0 or 1
    const int t256  = tid & 255;
    const int row   = t256 >> 3;       // 0..31  (unit_local*4 + gate)
    const int bb    = t256 & 7;        // batch
    const float* wrow = w_sm + row*516 + khalf*256;
    const float* hrow = h_smb + bb*516 + khalf*256;
    const size_t xg_idx = (size_t)bb * ((size_t)Nn*4*Hh)
                        + ((row & 3)*Hh + cta*8 + (row >> 2));

    float xg = (tid < 256) ? g_xproj[xg_idx] : 0.f;   // t = 0

    for (int t = 0; t < Nn; t++) {
        unsigned long long p0 = 0ull, p1 = 0ull, p2 = 0ull, p3 = 0ull;
#pragma unroll
        for (int k = 0; k < 256; k += 8) {
            ulonglong2 hv0 = *(const ulonglong2*)(hrow + k);
            ulonglong2 wv0 = *(const ulonglong2*)(wrow + k);
            ulonglong2 hv1 = *(const ulonglong2*)(hrow + k + 4);
            ulonglong2 wv1 = *(const ulonglong2*)(wrow + k + 4);
            FMA2(p0, hv0.x, wv0.x, p0);
            FMA2(p1, hv0.y, wv0.y, p1);
            FMA2(p2, hv1.x, wv1.x, p2);
            FMA2(p3, hv1.y, wv1.y, p3);
        }
        float2 f0 = *(float2*)&p0, f1 = *(float2*)&p1;
        float2 f2 = *(float2*)&p2, f3 = *(float2*)&p3;
        float acc = ((f0.x + f0.y) + (f1.x + f1.y))
                  + ((f2.x + f2.y) + (f3.x + f3.y));
        if (khalf) red1[t256] = acc;
        __syncthreads();
        if (!khalf) gsm[t256] = acc + red1[t256] + xg;
        __syncthreads();
        if (tid < 64) {
            int u = tid >> 3, b2 = tid & 7;
            float gi = gsm[(u*4 + 0)*8 + b2];
            float gf = gsm[(u*4 + 1)*8 + b2];
            float gg = gsm[(u*4 + 2)*8 + b2];
            float go = gsm[(u*4 + 3)*8 + b2];
            gi = 1.f/(1.f + __expf(-gi));
            gf = 1.f/(1.f + __expf(-gf));
            go = 1.f/(1.f + __expf(-go));
            gg = tanhf(gg);
            float c = gf * c_sm[tid] + gi * gg;
            c_sm[tid] = c;
            float hv = go * tanhf(c);
            int hu = cta*8 + u;
            g_hbuf[(t + 1) & 1][b2*Hh + hu] = hv;
            g_h[(size_t)b2*Nn*Hh + (size_t)t*Hh + hu] = hv;
            __threadfence();   // drain h stores to L2 before flag publish
        }
        __syncthreads();
        // prefetch next xg while warp 0 runs the barrier
        float xg_n = 0.f;
        if (tid < 256 && t + 1 < Nn)
            xg_n = g_xproj[xg_idx + (size_t)(t + 1) * (4*Hh)];
        // ---- R3 flat grid barrier (monotone epoch, count=64) ----
        if (tid == 0) {
            unsigned target = ep0 + (unsigned)t + 1u;
            unsigned a = atomicAdd(&g_bar_in, 1u);
            if (a == (unsigned)(LSTM_CTAS - 1)) {
                g_bar_in = 0u;
                __threadfence();
                atomicExch(&g_bar_epoch, target);
            } else {
                while (*((volatile unsigned*)&g_bar_epoch) < target) { }
            }
            __threadfence();
        }
        __syncthreads();
        const float* hb = g_hbuf[(t + 1) & 1];
        for (int i4 = tid; i4 < (Bsz*Hh)/4; i4 += LSTM_THREADS) {
            int b = i4 >> 7, k4 = (i4 & 127) * 4;
            float4 v = __ldcg((const float4*)&hb[b*Hh + k4]);
            *(float4*)&h_smb[b*516 + k4] = v;
        }
        __syncthreads();
        xg = xg_n;
    }
}

__global__ __launch_bounds__(256)
void softmax_kernel(const int* __restrict__ adj)
{
    const int row = blockIdx.x;
    const int i = row & (Nn - 1);
    float* s = g_scores + (size_t)row * Nn;
    const int* a = adj + (size_t)row * Nn;
    const int tid = threadIdx.x;
    float v[4]; int m[4];
    float mx = -3.0e30f; int any = 0;
#pragma unroll
    for (int q = 0; q < 4; q++) {
        int j = tid + q*256;
        int valid = (a[j] > 0) && (j != i);
        m[q] = valid; any |= valid;
        v[q] = valid ? s[j] : -3.0e30f;
        mx = fmaxf(mx, v[q]);
    }
    __shared__ float rbuf[8]; __shared__ int ibuf[8];
#pragma unroll
    for (int o = 16; o; o >>= 1) {
        mx = fmaxf(mx, __shfl_xor_sync(~0u, mx, o));
        any |= __shfl_xor_sync(~0u, any, o);
    }
    if ((tid & 31) == 0) { rbuf[tid >> 5] = mx; ibuf[tid >> 5] = any; }
    __syncthreads();
    if (tid < 32) {
        float m2 = (tid < 8) ? rbuf[tid] : -3.0e30f;
        int a2 = (tid < 8) ? ibuf[tid] : 0;
#pragma unroll
        for (int o = 4; o; o >>= 1) {
            m2 = fmaxf(m2, __shfl_xor_sync(~0u, m2, o));
            a2 |= __shfl_xor_sync(~0u, a2, o);
        }
        if (tid == 0) { rbuf[0] = m2; ibuf[0] = a2; }
    }
    __syncthreads();
    mx = rbuf[0]; any = ibuf[0];
    float e[4], sum = 0.f;
#pragma unroll
    for (int q = 0; q < 4; q++) { e[q] = m[q] ? __expf(v[q] - mx) : 0.f; sum += e[q]; }
    __syncthreads();
#pragma unroll
    for (int o = 16; o; o >>= 1) sum += __shfl_xor_sync(~0u, sum, o);
    if ((tid & 31) == 0) rbuf[tid >> 5] = sum;
    __syncthreads();
    if (tid < 32) {
        float s2 = (tid < 8) ? rbuf[tid] : 0.f;
#pragma unroll
        for (int o = 4; o; o >>= 1) s2 += __shfl_xor_sync(~0u, s2, o);
        if (tid == 0) rbuf[0] = s2;
    }
    __syncthreads();
    float inv = (rbuf[0] > 0.f) ? 1.f / rbuf[0] : 0.f;
#pragma unroll
    for (int q = 0; q < 4; q++) s[tid + q*256] = e[q] * inv;
    if (tid == 0) g_hasnb[row] = any;
}

extern "C" void kernel_launch(void* const* d_in, const int* in_sizes, int n_in,
                              void* d_out, int out_size)
{
    const float* feats = (const float*)d_in[0];
    const int*   adj   = (const int*)  d_in[1];
    const float* W_ih  = (const float*)d_in[2];
    const float* W_hh  = (const float*)d_in[3];
    const float* b_ih  = (const float*)d_in[4];
    const float* b_hh  = (const float*)d_in[5];
    const float* gx_W1 = (const float*)d_in[6];
    const float* gx_b1 = (const float*)d_in[7];
    const float* gx_W2 = (const float*)d_in[8];
    const float* gx_b2 = (const float*)d_in[9];
    const float* gz_W1 = (const float*)d_in[10];
    const float* gz_b1 = (const float*)d_in[11];
    const float* gz_W2 = (const float*)d_in[12];
    const float* gz_b2 = (const float*)d_in[13];
    const float* gv_W1 = (const float*)d_in[14];
    const float* gv_b1 = (const float*)d_in[15];
    const float* gv_W2 = (const float*)d_in[16];
    const float* gv_b2 = (const float*)d_in[17];
    const float* gn_W1 = (const float*)d_in[18];
    const float* gn_b1 = (const float*)d_in[19];
    const float* gn_W2 = (const float*)d_in[20];
    const float* gn_b2 = (const float*)d_in[21];
    const float* out_W = (const float*)d_in[22];
    const float* out_b = (const float*)d_in[23];
    float* out = (float*)d_out;
    (void)in_sizes; (void)n_in; (void)out_size;

    float *xproj, *h, *scores, *sagg, *t1, *t2, *ax, *av, *agg, *bsum;
    cudaGetSymbolAddress((void**)&xproj,  g_xproj);
    cudaGetSymbolAddress((void**)&h,      g_h);
    cudaGetSymbolAddress((void**)&scores, g_scores);
    cudaGetSymbolAddress((void**)&sagg,   g_sagg);
    cudaGetSymbolAddress((void**)&t1,     g_t1);
    cudaGetSymbolAddress((void**)&t2,     g_t2);
    cudaGetSymbolAddress((void**)&ax,     g_ax);
    cudaGetSymbolAddress((void**)&av,     g_av);
    cudaGetSymbolAddress((void**)&agg,    g_agg);
    cudaGetSymbolAddress((void**)&bsum,   g_bsum);

    const int lstm_smem = (32*516 + 8*516 + 256 + 256 + 64) * (int)sizeof(float);
    cudaFuncSetAttribute(lstm_kernel, cudaFuncAttributeMaxDynamicSharedMemorySize,
                         lstm_smem);

    bsum_kernel<<<8, 256>>>(b_ih, b_hh);
    // x_proj = feats @ W_ih^T + bsum  [8192, 2048]
    sgemm<1,0><<<dim3(4*Hh/128, MN/128, 1), 256>>>(feats, W_ih, bsum, xproj,
        Dd, Dd, Dd, 4*Hh, 0, 0, 0, 0);
    lstm_kernel<<<LSTM_CTAS, LSTM_THREADS, lstm_smem>>>(W_hh);
    // ax / av MLPs
    sgemm<1,1><<<dim3(Mm/128, MN/128, 1), 256>>>(h,  gx_W1, gx_b1, t1, Hh, Hh, Hh, Mm, 0,0,0, 0);
    sgemm<1,0><<<dim3(Mm/128, MN/128, 1), 256>>>(t1, gx_W2, gx_b2, ax, Mm, Mm, Mm, Mm, 0,0,0, 0);
    sgemm<1,1><<<dim3(Mm/128, MN/128, 1), 256>>>(h,  gv_W1, gv_b1, t1, Hh, Hh, Hh, Mm, 0,0,0, 0);
    sgemm<1,0><<<dim3(Mm/128, MN/128, 1), 256>>>(t1, gv_W2, gv_b2, av, Mm, Mm, Mm, Mm, 0,0,0, 0);
    // scores[b] = ax_b @ av_b^T
    sgemm<1,0><<<dim3(Nn/128, Nn/128, Bsz), 256>>>(ax, av, nullptr, scores,
        Mm, Mm, Mm, Nn, (long long)Nn*Mm, (long long)Nn*Mm, (long long)Nn*Nn, 0);
    softmax_kernel<<<MN, 256>>>(adj);
    // sagg[b] = w_b @ h_b
    sgemm<0,0><<<dim3(Hh/128, Nn/128, Bsz), 256>>>(scores, h, nullptr, sagg,
        Nn, Nn, Hh, Hh, (long long)Nn*Nn, (long long)Nn*Hh, (long long)Nn*Hh, 0);
    // agg = MLP(MLP(sagg; gz); gn)
    sgemm<1,1><<<dim3(Mm/128, MN/128, 1), 256>>>(sagg, gz_W1, gz_b1, t1, Hh, Hh, Hh, Mm, 0,0,0, 0);
    sgemm<1,0><<<dim3(Mm/128, MN/128, 1), 256>>>(t1, gz_W2, gz_b2, t2, Mm, Mm, Mm, Mm, 0,0,0, 0);
    sgemm<1,1><<<dim3(Mm/128, MN/128, 1), 256>>>(t2, gn_W1, gn_b1, t1, Mm, Mm, Mm, Mm, 0,0,0, 0);
    sgemm<1,0><<<dim3(Oo/128, MN/128, 1), 256>>>(t1, gn_W2, gn_b2, agg, Mm, Mm, Mm, Oo, 0,0,0, 0);
    zeroagg_kernel<<<MN, Oo>>>();
    // out = h @ out_W[:, :H]^T + out_b ; out += agg @ out_W[:, H:]^T
    sgemm<1,0><<<dim3(Oo/128, MN/128, 1), 256>>>(h, out_W, out_b, out,
        Hh, Hh, Hh + Oo, Oo, 0, 0, 0, 0);
    sgemm<1,0><<<dim3(Oo/128, MN/128, 1), 256>>>(agg, out_W + Hh, nullptr, out,
        Oo, Oo, Hh + Oo, Oo, 0, 0, 0, 1);
}

// round 15
// speedup vs baseline: 1.2613x; 1.2613x over previous
#include <cuda_runtime.h>
#include <math.h>

#define Bsz 8
#define Nn  1024
#define Dd  256
#define Hh  512
#define Mm  256
#define Oo  256
#define MN  (Bsz*Nn)
#define LSTM_CTAS 128

#define FMA2(d,a,b,c) asm("fma.rn.f32x2 %0, %1, %2, %3;" \
    : "=l"(d) : "l"(a), "l"(b), "l"(c))

__device__ float g_xproj[(size_t)MN*4*Hh];
__device__ float g_h[(size_t)MN*Hh];
__device__ float g_scores[(size_t)Bsz*Nn*Nn];
__device__ float g_sagg[(size_t)MN*Hh];
__device__ float g_t1[(size_t)MN*Mm];
__device__ float g_t2[(size_t)MN*Mm];
__device__ float g_ax[(size_t)MN*Mm];
__device__ float g_av[(size_t)MN*Mm];
__device__ float g_agg[(size_t)MN*Oo];
__device__ float g_bsum[4*Hh];
__device__ float g_hbuf[2][Bsz*Hh];
__device__ int   g_hasnb[MN];
__device__ unsigned g_bar_in = 0;
__device__ unsigned g_bar_epoch = 0;

__global__ void bsum_kernel(const float* __restrict__ a, const float* __restrict__ b) {
    int i = blockIdx.x * 256 + threadIdx.x;
    if (i < 4*Hh) g_bsum[i] = a[i] + b[i];
}

__global__ void zeroagg_kernel() {
    int row = blockIdx.x;
    if (!g_hasnb[row]) g_agg[(size_t)row*Oo + threadIdx.x] = 0.f;
}

// C = A * op(B) (+bias)(ReLU)(+=C). 128x128 tile, K-tile 8, 256 thr, 8x8 micro.
// 2-stage double-buffered smem pipeline; packed f32x2 FMA.  (proven 64.4us)
template<int TRANSB, int RELU>
__global__ __launch_bounds__(256)
void sgemm(const float* __restrict__ A, const float* __restrict__ B,
           const float* __restrict__ bias, float* __restrict__ C,
           int K, int lda, int ldb, int ldc,
           long long sA, long long sB, long long sC, int beta)
{
    __shared__ float As[2][8][132];
    __shared__ float Bs[2][8][132];
    const int tid = threadIdx.x;
    const int m0 = blockIdx.y * 128, n0 = blockIdx.x * 128;
    A += (long long)blockIdx.z * sA;
    B += (long long)blockIdx.z * sB;
    C += (long long)blockIdx.z * sC;

    unsigned long long pacc[8][4];
#pragma unroll
    for (int i = 0; i < 8; i++)
#pragma unroll
        for (int j = 0; j < 4; j++) pacc[i][j] = 0ull;

    const int ty = tid >> 4, tx = tid & 15;
    const int am = tid >> 1, akq = (tid & 1) * 4;
    const int bk = tid >> 5, bnq = (tid & 31) * 4;

    float4 pa = *(const float4*)&A[(size_t)(m0 + am) * lda + akq];
    float4 pb;
    if (TRANSB) pb = *(const float4*)&B[(size_t)(n0 + am) * ldb + akq];
    else        pb = *(const float4*)&B[(size_t)bk * ldb + n0 + bnq];

    int cur = 0;
    As[0][akq+0][am] = pa.x; As[0][akq+1][am] = pa.y;
    As[0][akq+2][am] = pa.z; As[0][akq+3][am] = pa.w;
    if (TRANSB) {
        Bs[0][akq+0][am] = pb.x; Bs[0][akq+1][am] = pb.y;
        Bs[0][akq+2][am] = pb.z; Bs[0][akq+3][am] = pb.w;
    } else {
        *(float4*)&Bs[0][bk][bnq] = pb;
    }
    __syncthreads();

    const int NT = K >> 3;
    for (int kt = 0; kt < NT; kt++) {
        if (kt + 1 < NT) {
            int k0 = (kt + 1) << 3;
            pa = *(const float4*)&A[(size_t)(m0 + am) * lda + k0 + akq];
            if (TRANSB) pb = *(const float4*)&B[(size_t)(n0 + am) * ldb + k0 + akq];
            else        pb = *(const float4*)&B[(size_t)(k0 + bk) * ldb + n0 + bnq];
        }
#pragma unroll
        for (int k = 0; k < 8; k++) {
            float a[8];
            *(float4*)&a[0] = *(const float4*)&As[cur][k][ty*8];
            *(float4*)&a[4] = *(const float4*)&As[cur][k][ty*8 + 4];
            ulonglong2 q0 = *(const ulonglong2*)&Bs[cur][k][tx*8];
            ulonglong2 q1 = *(const ulonglong2*)&Bs[cur][k][tx*8 + 4];
            unsigned long long bp0 = q0.x, bp1 = q0.y, bp2 = q1.x, bp3 = q1.y;
#pragma unroll
            for (int i = 0; i < 8; i++) {
                unsigned au = __float_as_uint(a[i]);
                unsigned long long ai;
                asm("mov.b64 %0, {%1, %1};" : "=l"(ai) : "r"(au));
                FMA2(pacc[i][0], ai, bp0, pacc[i][0]);
                FMA2(pacc[i][1], ai, bp1, pacc[i][1]);
                FMA2(pacc[i][2], ai, bp2, pacc[i][2]);
                FMA2(pacc[i][3], ai, bp3, pacc[i][3]);
            }
        }
        if (kt + 1 < NT) {
            int nxt = cur ^ 1;
            As[nxt][akq+0][am] = pa.x; As[nxt][akq+1][am] = pa.y;
            As[nxt][akq+2][am] = pa.z; As[nxt][akq+3][am] = pa.w;
            if (TRANSB) {
                Bs[nxt][akq+0][am] = pb.x; Bs[nxt][akq+1][am] = pb.y;
                Bs[nxt][akq+2][am] = pb.z; Bs[nxt][akq+3][am] = pb.w;
            } else {
                *(float4*)&Bs[nxt][bk][bnq] = pb;
            }
            __syncthreads();
            cur = nxt;
        }
    }

    float bv[8];
#pragma unroll
    for (int j = 0; j < 8; j++) bv[j] = bias ? bias[n0 + tx*8 + j] : 0.f;
#pragma unroll
    for (int i = 0; i < 8; i++) {
        float accf[8];
#pragma unroll
        for (int j4 = 0; j4 < 4; j4++) {
            float2 v = *(float2*)&pacc[i][j4];
            accf[2*j4]   = v.x;
            accf[2*j4+1] = v.y;
        }
        float* cp = C + (size_t)(m0 + ty*8 + i) * ldc + n0 + tx*8;
#pragma unroll
        for (int j = 0; j < 8; j += 4) {
            float4 r;
            r.x = accf[j+0] + bv[j+0]; r.y = accf[j+1] + bv[j+1];
            r.z = accf[j+2] + bv[j+2]; r.w = accf[j+3] + bv[j+3];
            if (RELU) {
                r.x = fmaxf(r.x, 0.f); r.y = fmaxf(r.y, 0.f);
                r.z = fmaxf(r.z, 0.f); r.w = fmaxf(r.w, 0.f);
            }
            if (beta) {
                float4 o = *(const float4*)(cp + j);
                r.x += o.x; r.y += o.y; r.z += o.z; r.w += o.w;
            }
            *(float4*)(cp + j) = r;
        }
    }
}

// Persistent LSTM — R3-proven kernel, verbatim (empirical optimum).
// CTA c owns hidden units [4c,4c+4) -> 16 gate rows in SMEM; flat epoch barrier.
__global__ __launch_bounds__(256, 1)
void lstm_kernel(const float* __restrict__ W_hh)
{
    extern __shared__ float sh[];
    float* w_sm  = sh;                 // 16*516
    float* h_smb = w_sm + 16*516;      // 8*516
    float* red1  = h_smb + 8*516;      // 128
    float* gsm   = red1 + 128;         // 128
    float* c_sm  = gsm + 128;          // 32

    const int tid = threadIdx.x;
    const int cta = blockIdx.x;

    for (int i = tid; i < 16*512; i += 256) {
        int r = i >> 9, k = i & 511;
        int grow = ((r & 3) << 9) + cta*4 + (r >> 2);   // gate*512 + unit
        w_sm[r*516 + k] = W_hh[(size_t)grow*Hh + k];
    }
    for (int i = tid; i < 8*516; i += 256) h_smb[i] = 0.f;
    if (tid < 32) c_sm[tid] = 0.f;
    unsigned ep0 = atomicAdd(&g_bar_epoch, 0u);
    __syncthreads();

    const int warp = tid >> 5, lane = tid & 31;
    const int khalf = warp >> 2;
    const int row = (warp & 3)*4 + (lane >> 3);  // unit_local*4+gate id in 0..15
    const int bb = lane & 7;
    const float* wrow = w_sm + row*516 + khalf*256;
    const float* hrow = h_smb + bb*516 + khalf*256;
    const size_t xg_idx = (size_t)bb * ((size_t)Nn*4*Hh)
                        + ((row & 3)*Hh + cta*4 + (row >> 2));

    for (int t = 0; t < Nn; t++) {
        float xg = 0.f;
        if (tid < 128) xg = g_xproj[xg_idx + (size_t)t * (4*Hh)];
        float a0 = 0.f, a1 = 0.f, a2 = 0.f, a3 = 0.f;
#pragma unroll 16
        for (int k = 0; k < 256; k += 4) {
            float4 hv = *(const float4*)(hrow + k);
            float4 wv = *(const float4*)(wrow + k);
            a0 += hv.x*wv.x; a1 += hv.y*wv.y;
            a2 += hv.z*wv.z; a3 += hv.w*wv.w;
        }
        float acc = (a0 + a1) + (a2 + a3);
        if (tid >= 128) red1[row*8 + bb] = acc;
        __syncthreads();
        if (tid < 128) gsm[tid] = acc + red1[tid] + xg;
        __syncthreads();
        if (tid < 32) {
            int u = tid >> 3, b2 = tid & 7;
            float gi = gsm[(u*4 + 0)*8 + b2];
            float gf = gsm[(u*4 + 1)*8 + b2];
            float gg = gsm[(u*4 + 2)*8 + b2];
            float go = gsm[(u*4 + 3)*8 + b2];
            gi = 1.f/(1.f + __expf(-gi));
            gf = 1.f/(1.f + __expf(-gf));
            go = 1.f/(1.f + __expf(-go));
            gg = tanhf(gg);
            float c = gf * c_sm[tid] + gi * gg;
            c_sm[tid] = c;
            float hv = go * tanhf(c);
            int hu = cta*4 + u;
            g_hbuf[(t + 1) & 1][b2*Hh + hu] = hv;
            g_h[(size_t)b2*Nn*Hh + (size_t)t*Hh + hu] = hv;
        }
        __syncthreads();
        if (tid == 0) {
            __threadfence();
            unsigned target = ep0 + (unsigned)t + 1u;
            unsigned a = atomicAdd(&g_bar_in, 1u);
            if (a == (unsigned)(LSTM_CTAS - 1)) {
                g_bar_in = 0u;
                __threadfence();
                atomicExch(&g_bar_epoch, target);
            } else {
                while (*((volatile unsigned*)&g_bar_epoch) < target) { }
            }
            __threadfence();
        }
        __syncthreads();
        const float* hb = g_hbuf[(t + 1) & 1];
        for (int i4 = tid; i4 < (Bsz*Hh)/4; i4 += 256) {
            int b = i4 >> 7, k4 = (i4 & 127) * 4;
            float4 v = __ldcg((const float4*)&hb[b*Hh + k4]);
            *(float4*)&h_smb[b*516 + k4] = v;
        }
        __syncthreads();
    }
}

__global__ __launch_bounds__(256)
void softmax_kernel(const int* __restrict__ adj)
{
    const int row = blockIdx.x;
    const int i = row & (Nn - 1);
    float* s = g_scores + (size_t)row * Nn;
    const int* a = adj + (size_t)row * Nn;
    const int tid = threadIdx.x;
    float v[4]; int m[4];
    float mx = -3.0e30f; int any = 0;
#pragma unroll
    for (int q = 0; q < 4; q++) {
        int j = tid + q*256;
        int valid = (a[j] > 0) && (j != i);
        m[q] = valid; any |= valid;
        v[q] = valid ? s[j] : -3.0e30f;
        mx = fmaxf(mx, v[q]);
    }
    __shared__ float rbuf[8]; __shared__ int ibuf[8];
#pragma unroll
    for (int o = 16; o; o >>= 1) {
        mx = fmaxf(mx, __shfl_xor_sync(~0u, mx, o));
        any |= __shfl_xor_sync(~0u, any, o);
    }
    if ((tid & 31) == 0) { rbuf[tid >> 5] = mx; ibuf[tid >> 5] = any; }
    __syncthreads();
    if (tid < 32) {
        float m2 = (tid < 8) ? rbuf[tid] : -3.0e30f;
        int a2 = (tid < 8) ? ibuf[tid] : 0;
#pragma unroll
        for (int o = 4; o; o >>= 1) {
            m2 = fmaxf(m2, __shfl_xor_sync(~0u, m2, o));
            a2 |= __shfl_xor_sync(~0u, a2, o);
        }
        if (tid == 0) { rbuf[0] = m2; ibuf[0] = a2; }
    }
    __syncthreads();
    mx = rbuf[0]; any = ibuf[0];
    float e[4], sum = 0.f;
#pragma unroll
    for (int q = 0; q < 4; q++) { e[q] = m[q] ? __expf(v[q] - mx) : 0.f; sum += e[q]; }
    __syncthreads();
#pragma unroll
    for (int o = 16; o; o >>= 1) sum += __shfl_xor_sync(~0u, sum, o);
    if ((tid & 31) == 0) rbuf[tid >> 5] = sum;
    __syncthreads();
    if (tid < 32) {
        float s2 = (tid < 8) ? rbuf[tid] : 0.f;
#pragma unroll
        for (int o = 4; o; o >>= 1) s2 += __shfl_xor_sync(~0u, s2, o);
        if (tid == 0) rbuf[0] = s2;
    }
    __syncthreads();
    float inv = (rbuf[0] > 0.f) ? 1.f / rbuf[0] : 0.f;
#pragma unroll
    for (int q = 0; q < 4; q++) s[tid + q*256] = e[q] * inv;
    if (tid == 0) g_hasnb[row] = any;
}

extern "C" void kernel_launch(void* const* d_in, const int* in_sizes, int n_in,
                              void* d_out, int out_size)
{
    const float* feats = (const float*)d_in[0];
    const int*   adj   = (const int*)  d_in[1];
    const float* W_ih  = (const float*)d_in[2];
    const float* W_hh  = (const float*)d_in[3];
    const float* b_ih  = (const float*)d_in[4];
    const float* b_hh  = (const float*)d_in[5];
    const float* gx_W1 = (const float*)d_in[6];
    const float* gx_b1 = (const float*)d_in[7];
    const float* gx_W2 = (const float*)d_in[8];
    const float* gx_b2 = (const float*)d_in[9];
    const float* gz_W1 = (const float*)d_in[10];
    const float* gz_b1 = (const float*)d_in[11];
    const float* gz_W2 = (const float*)d_in[12];
    const float* gz_b2 = (const float*)d_in[13];
    const float* gv_W1 = (const float*)d_in[14];
    const float* gv_b1 = (const float*)d_in[15];
    const float* gv_W2 = (const float*)d_in[16];
    const float* gv_b2 = (const float*)d_in[17];
    const float* gn_W1 = (const float*)d_in[18];
    const float* gn_b1 = (const float*)d_in[19];
    const float* gn_W2 = (const float*)d_in[20];
    const float* gn_b2 = (const float*)d_in[21];
    const float* out_W = (const float*)d_in[22];
    const float* out_b = (const float*)d_in[23];
    float* out = (float*)d_out;
    (void)in_sizes; (void)n_in; (void)out_size;

    float *xproj, *h, *scores, *sagg, *t1, *t2, *ax, *av, *agg, *bsum;
    cudaGetSymbolAddress((void**)&xproj,  g_xproj);
    cudaGetSymbolAddress((void**)&h,      g_h);
    cudaGetSymbolAddress((void**)&scores, g_scores);
    cudaGetSymbolAddress((void**)&sagg,   g_sagg);
    cudaGetSymbolAddress((void**)&t1,     g_t1);
    cudaGetSymbolAddress((void**)&t2,     g_t2);
    cudaGetSymbolAddress((void**)&ax,     g_ax);
    cudaGetSymbolAddress((void**)&av,     g_av);
    cudaGetSymbolAddress((void**)&agg,    g_agg);
    cudaGetSymbolAddress((void**)&bsum,   g_bsum);

    const int lstm_smem = (16*516 + 8*516 + 128 + 128 + 32) * (int)sizeof(float);
    cudaFuncSetAttribute(lstm_kernel, cudaFuncAttributeMaxDynamicSharedMemorySize,
                         lstm_smem);

    bsum_kernel<<<8, 256>>>(b_ih, b_hh);
    // x_proj = feats @ W_ih^T + bsum  [8192, 2048]
    sgemm<1,0><<<dim3(4*Hh/128, MN/128, 1), 256>>>(feats, W_ih, bsum, xproj,
        Dd, Dd, Dd, 4*Hh, 0, 0, 0, 0);
    lstm_kernel<<<LSTM_CTAS, 256, lstm_smem>>>(W_hh);
    // ax / av MLPs
    sgemm<1,1><<<dim3(Mm/128, MN/128, 1), 256>>>(h,  gx_W1, gx_b1, t1, Hh, Hh, Hh, Mm, 0,0,0, 0);
    sgemm<1,0><<<dim3(Mm/128, MN/128, 1), 256>>>(t1, gx_W2, gx_b2, ax, Mm, Mm, Mm, Mm, 0,0,0, 0);
    sgemm<1,1><<<dim3(Mm/128, MN/128, 1), 256>>>(h,  gv_W1, gv_b1, t1, Hh, Hh, Hh, Mm, 0,0,0, 0);
    sgemm<1,0><<<dim3(Mm/128, MN/128, 1), 256>>>(t1, gv_W2, gv_b2, av, Mm, Mm, Mm, Mm, 0,0,0, 0);
    // scores[b] = ax_b @ av_b^T
    sgemm<1,0><<<dim3(Nn/128, Nn/128, Bsz), 256>>>(ax, av, nullptr, scores,
        Mm, Mm, Mm, Nn, (long long)Nn*Mm, (long long)Nn*Mm, (long long)Nn*Nn, 0);
    softmax_kernel<<<MN, 256>>>(adj);
    // sagg[b] = w_b @ h_b
    sgemm<0,0><<<dim3(Hh/128, Nn/128, Bsz), 256>>>(scores, h, nullptr, sagg,
        Nn, Nn, Hh, Hh, (long long)Nn*Nn, (long long)Nn*Hh, (long long)Nn*Hh, 0);
    // agg = MLP(MLP(sagg; gz); gn)
    sgemm<1,1><<<dim3(Mm/128, MN/128, 1), 256>>>(sagg, gz_W1, gz_b1, t1, Hh, Hh, Hh, Mm, 0,0,0, 0);
    sgemm<1,0><<<dim3(Mm/128, MN/128, 1), 256>>>(t1, gz_W2, gz_b2, t2, Mm, Mm, Mm, Mm, 0,0,0, 0);
    sgemm<1,1><<<dim3(Mm/128, MN/128, 1), 256>>>(t2, gn_W1, gn_b1, t1, Mm, Mm, Mm, Mm, 0,0,0, 0);
    sgemm<1,0><<<dim3(Oo/128, MN/128, 1), 256>>>(t1, gn_W2, gn_b2, agg, Mm, Mm, Mm, Oo, 0,0,0, 0);
    zeroagg_kernel<<<MN, Oo>>>();
    // out = h @ out_W[:, :H]^T + out_b ; out += agg @ out_W[:, H:]^T
    sgemm<1,0><<<dim3(Oo/128, MN/128, 1), 256>>>(h, out_W, out_b, out,
        Hh, Hh, Hh + Oo, Oo, 0, 0, 0, 0);
    sgemm<1,0><<<dim3(Oo/128, MN/128, 1), 256>>>(agg, out_W + Hh, nullptr, out,
        Oo, Oo, Hh + Oo, Oo, 0, 0, 0, 1);
}